// round 1
// baseline (speedup 1.0000x reference)
#include <cuda_runtime.h>

#define BATCH 4
#define CH    256
#define SP    4096   // 64*64 spatial == attention rows
#define DH    256    // head dim == CH

// Scratch (allocation-free rule: __device__ globals)
__device__ float g_q[BATCH * CH * SP];
__device__ float g_k[BATCH * CH * SP];
__device__ float g_v[BATCH * CH * SP];
__device__ float g_a[BATCH * CH * SP];

// ---------------------------------------------------------------------------
// Kernel 1: fused Q/K/V 1x1 conv.  Y[o][s] = b[o] + sum_c W[o][c] x[c][s]
// grid (32 s-tiles, 4 c-tiles, 12 = batch*3 + which), 256 threads
// CTA tile: 64 (out ch) x 128 (spatial), K-chunks of 16
// ---------------------------------------------------------------------------
__global__ __launch_bounds__(256) void qkv_kernel(
    const float* __restrict__ x,
    const float* __restrict__ Wq, const float* __restrict__ bq,
    const float* __restrict__ Wk, const float* __restrict__ bk,
    const float* __restrict__ Wv, const float* __restrict__ bv)
{
    __shared__ float Ws[16][68];    // [k][m], padded
    __shared__ float Xs[16][128];   // [k][n]

    int z = blockIdx.z;
    int b = z / 3, w = z % 3;
    const float* W    = (w == 0) ? Wq : (w == 1) ? Wk : Wv;
    const float* bias = (w == 0) ? bq : (w == 1) ? bk : bv;
    float* out        = (w == 0) ? g_q : (w == 1) ? g_k : g_v;

    int m0 = blockIdx.y * 64;
    int s0 = blockIdx.x * 128;
    int tid = threadIdx.x;
    int ty = tid >> 4, tx = tid & 15;

    float acc[4][8];
#pragma unroll
    for (int i = 0; i < 4; i++)
#pragma unroll
        for (int j = 0; j < 8; j++) acc[i][j] = 0.0f;

    const float* xb = x + (size_t)b * CH * SP;

    for (int k0 = 0; k0 < CH; k0 += 16) {
        // load W chunk [64 m][16 k] -> Ws[k][m]
        {
            int mm = tid & 63, kk4 = (tid >> 6) << 2;
            float4 wv = *(const float4*)&W[(m0 + mm) * CH + k0 + kk4];
            Ws[kk4 + 0][mm] = wv.x;
            Ws[kk4 + 1][mm] = wv.y;
            Ws[kk4 + 2][mm] = wv.z;
            Ws[kk4 + 3][mm] = wv.w;
        }
        // load X chunk [16 k][128 n]
        {
            int kk = tid >> 4, nn = (tid & 15) * 8;
            const float* xp = xb + (size_t)(k0 + kk) * SP + s0 + nn;
            *(float4*)&Xs[kk][nn]     = *(const float4*)xp;
            *(float4*)&Xs[kk][nn + 4] = *(const float4*)(xp + 4);
        }
        __syncthreads();
#pragma unroll
        for (int k = 0; k < 16; k++) {
            float4 a  = *(const float4*)&Ws[k][ty * 4];
            float4 b0 = *(const float4*)&Xs[k][tx * 8];
            float4 b1 = *(const float4*)&Xs[k][tx * 8 + 4];
            float av[4] = {a.x, a.y, a.z, a.w};
            float bw[8] = {b0.x, b0.y, b0.z, b0.w, b1.x, b1.y, b1.z, b1.w};
#pragma unroll
            for (int i = 0; i < 4; i++)
#pragma unroll
                for (int j = 0; j < 8; j++)
                    acc[i][j] = fmaf(av[i], bw[j], acc[i][j]);
        }
        __syncthreads();
    }

    float* ob = out + (size_t)b * CH * SP;
#pragma unroll
    for (int i = 0; i < 4; i++) {
        int m = m0 + ty * 4 + i;
        float bi = bias[m];
        float4 r0, r1;
        r0.x = acc[i][0] + bi; r0.y = acc[i][1] + bi;
        r0.z = acc[i][2] + bi; r0.w = acc[i][3] + bi;
        r1.x = acc[i][4] + bi; r1.y = acc[i][5] + bi;
        r1.z = acc[i][6] + bi; r1.w = acc[i][7] + bi;
        float* op = &ob[(size_t)m * SP + s0 + tx * 8];
        *(float4*)op       = r0;
        *(float4*)(op + 4) = r1;
    }
}

// ---------------------------------------------------------------------------
// Kernel 2: flash attention, fp32.  Rows = flat view [4096 x 256] of conv out.
// grid (64 row-tiles, 4 batches), 256 threads, Br = Bc = 64.
// smem: Qs[64][260] Ks[64][260] Vs[64][256] Ps[64][68]  = 216064 B
// thread (ty,tx): S rows 4ty+i, S cols tx+16j; O rows 4ty+i, O cols 4tx+64v+w
// ---------------------------------------------------------------------------
#define QS_STRIDE 260   // 260*4B = 65*16B -> float4-aligned rows, conflict-lite
#define PS_STRIDE 68

__global__ __launch_bounds__(256, 1) void attn_kernel()
{
    extern __shared__ float sm[];
    float* Qs = sm;                       // [64][260]
    float* Ks = Qs + 64 * QS_STRIDE;      // [64][260]
    float* Vs = Ks + 64 * QS_STRIDE;      // [64][256]
    float* Ps = Vs + 64 * 256;            // [64][68]

    int b  = blockIdx.y;
    int n0 = blockIdx.x * 64;
    const float* Qg = g_q + (size_t)b * CH * SP + (size_t)n0 * DH;
    const float* Kg = g_k + (size_t)b * CH * SP;
    const float* Vg = g_v + (size_t)b * CH * SP;

    int tid = threadIdx.x;
    int ty = tid >> 4, tx = tid & 15;

    // load Q tile once (contiguous 64KB block)
    for (int idx = tid; idx < 64 * 64; idx += 256) {
        int r = idx >> 6, d4 = (idx & 63) << 2;
        *(float4*)&Qs[r * QS_STRIDE + d4] = *(const float4*)&Qg[r * DH + d4];
    }

    float mr[4], lr[4], o[4][16];
#pragma unroll
    for (int i = 0; i < 4; i++) {
        mr[i] = -1e30f;
        lr[i] = 0.0f;
#pragma unroll
        for (int c = 0; c < 16; c++) o[i][c] = 0.0f;
    }

    for (int mt = 0; mt < 64; mt++) {
        const float* Kb = Kg + (size_t)mt * 64 * DH;
        const float* Vb = Vg + (size_t)mt * 64 * DH;
        __syncthreads();   // protect Ks/Vs/Ps from previous iteration readers
        for (int idx = tid; idx < 64 * 64; idx += 256) {
            int r = idx >> 6, d4 = (idx & 63) << 2;
            *(float4*)&Ks[r * QS_STRIDE + d4] = *(const float4*)&Kb[r * DH + d4];
            *(float4*)&Vs[r * 256 + d4]       = *(const float4*)&Vb[r * DH + d4];
        }
        __syncthreads();

        // S = Q K^T  (64x64, k=256)
        float s[4][4];
#pragma unroll
        for (int i = 0; i < 4; i++)
#pragma unroll
            for (int j = 0; j < 4; j++) s[i][j] = 0.0f;

#pragma unroll 2
        for (int d = 0; d < 256; d += 4) {
            float4 aa[4], bb[4];
#pragma unroll
            for (int i = 0; i < 4; i++)
                aa[i] = *(const float4*)&Qs[(ty * 4 + i) * QS_STRIDE + d];
#pragma unroll
            for (int j = 0; j < 4; j++)
                bb[j] = *(const float4*)&Ks[(tx + 16 * j) * QS_STRIDE + d];
#pragma unroll
            for (int i = 0; i < 4; i++)
#pragma unroll
                for (int j = 0; j < 4; j++) {
                    s[i][j] = fmaf(aa[i].x, bb[j].x, s[i][j]);
                    s[i][j] = fmaf(aa[i].y, bb[j].y, s[i][j]);
                    s[i][j] = fmaf(aa[i].z, bb[j].z, s[i][j]);
                    s[i][j] = fmaf(aa[i].w, bb[j].w, s[i][j]);
                }
        }

        // online softmax update (row groups = 16 lanes sharing ty)
#pragma unroll
        for (int i = 0; i < 4; i++) {
            float mb = fmaxf(fmaxf(s[i][0], s[i][1]), fmaxf(s[i][2], s[i][3]));
            mb = fmaxf(mb, __shfl_xor_sync(0xffffffffu, mb, 8));
            mb = fmaxf(mb, __shfl_xor_sync(0xffffffffu, mb, 4));
            mb = fmaxf(mb, __shfl_xor_sync(0xffffffffu, mb, 2));
            mb = fmaxf(mb, __shfl_xor_sync(0xffffffffu, mb, 1));
            float mn = fmaxf(mr[i], mb);
            float sc = __expf(mr[i] - mn);
            mr[i] = mn;
            float rs = 0.0f;
#pragma unroll
            for (int j = 0; j < 4; j++) {
                float p = __expf(s[i][j] - mn);
                s[i][j] = p;
                rs += p;
            }
            rs += __shfl_xor_sync(0xffffffffu, rs, 8);
            rs += __shfl_xor_sync(0xffffffffu, rs, 4);
            rs += __shfl_xor_sync(0xffffffffu, rs, 2);
            rs += __shfl_xor_sync(0xffffffffu, rs, 1);
            lr[i] = lr[i] * sc + rs;
#pragma unroll
            for (int c = 0; c < 16; c++) o[i][c] *= sc;
#pragma unroll
            for (int j = 0; j < 4; j++)
                Ps[(ty * 4 + i) * PS_STRIDE + tx + 16 * j] = s[i][j];
        }
        __syncthreads();

        // O += P V   (64x256, k=64)
#pragma unroll 2
        for (int k = 0; k < 64; k++) {
            float av[4];
#pragma unroll
            for (int i = 0; i < 4; i++) av[i] = Ps[(ty * 4 + i) * PS_STRIDE + k];
#pragma unroll
            for (int v = 0; v < 4; v++) {
                float4 bv = *(const float4*)&Vs[k * 256 + tx * 4 + v * 64];
#pragma unroll
                for (int i = 0; i < 4; i++) {
                    o[i][v * 4 + 0] = fmaf(av[i], bv.x, o[i][v * 4 + 0]);
                    o[i][v * 4 + 1] = fmaf(av[i], bv.y, o[i][v * 4 + 1]);
                    o[i][v * 4 + 2] = fmaf(av[i], bv.z, o[i][v * 4 + 2]);
                    o[i][v * 4 + 3] = fmaf(av[i], bv.w, o[i][v * 4 + 3]);
                }
            }
        }
    }

    // epilogue: normalize and store attn rows (row-major [4096][256] flat)
    float* Ab = g_a + (size_t)b * CH * SP;
#pragma unroll
    for (int i = 0; i < 4; i++) {
        float inv = 1.0f / lr[i];
        int row = n0 + ty * 4 + i;
#pragma unroll
        for (int v = 0; v < 4; v++) {
            float4 r;
            r.x = o[i][v * 4 + 0] * inv;
            r.y = o[i][v * 4 + 1] * inv;
            r.z = o[i][v * 4 + 2] * inv;
            r.w = o[i][v * 4 + 3] * inv;
            *(float4*)&Ab[(size_t)row * DH + tx * 4 + v * 64] = r;
        }
    }
}

// ---------------------------------------------------------------------------
// Kernel 3: out = x + Wu * attn + bu   (attn flat buffer viewed as [CH][SP])
// grid (32 s-tiles, 4 c-tiles, 4 batches), 256 threads
// ---------------------------------------------------------------------------
__global__ __launch_bounds__(256) void out_kernel(
    const float* __restrict__ x, const float* __restrict__ Wu,
    const float* __restrict__ bu, float* __restrict__ out)
{
    __shared__ float Ws[16][68];
    __shared__ float Xs[16][128];

    int b = blockIdx.z;
    int m0 = blockIdx.y * 64;
    int s0 = blockIdx.x * 128;
    int tid = threadIdx.x;
    int ty = tid >> 4, tx = tid & 15;

    float acc[4][8];
#pragma unroll
    for (int i = 0; i < 4; i++)
#pragma unroll
        for (int j = 0; j < 8; j++) acc[i][j] = 0.0f;

    const float* Ab = g_a + (size_t)b * CH * SP;

    for (int k0 = 0; k0 < CH; k0 += 16) {
        {
            int mm = tid & 63, kk4 = (tid >> 6) << 2;
            float4 wv = *(const float4*)&Wu[(m0 + mm) * CH + k0 + kk4];
            Ws[kk4 + 0][mm] = wv.x;
            Ws[kk4 + 1][mm] = wv.y;
            Ws[kk4 + 2][mm] = wv.z;
            Ws[kk4 + 3][mm] = wv.w;
        }
        {
            int kk = tid >> 4, nn = (tid & 15) * 8;
            const float* ap = Ab + (size_t)(k0 + kk) * SP + s0 + nn;
            *(float4*)&Xs[kk][nn]     = *(const float4*)ap;
            *(float4*)&Xs[kk][nn + 4] = *(const float4*)(ap + 4);
        }
        __syncthreads();
#pragma unroll
        for (int k = 0; k < 16; k++) {
            float4 a  = *(const float4*)&Ws[k][ty * 4];
            float4 b0 = *(const float4*)&Xs[k][tx * 8];
            float4 b1 = *(const float4*)&Xs[k][tx * 8 + 4];
            float av[4] = {a.x, a.y, a.z, a.w};
            float bw[8] = {b0.x, b0.y, b0.z, b0.w, b1.x, b1.y, b1.z, b1.w};
#pragma unroll
            for (int i = 0; i < 4; i++)
#pragma unroll
                for (int j = 0; j < 8; j++)
                    acc[i][j] = fmaf(av[i], bw[j], acc[i][j]);
        }
        __syncthreads();
    }

#pragma unroll
    for (int i = 0; i < 4; i++) {
        int m = m0 + ty * 4 + i;
        float bi = bu[m];
        size_t base = (size_t)b * CH * SP + (size_t)m * SP + s0 + tx * 8;
        float4 x0 = *(const float4*)&x[base];
        float4 x1 = *(const float4*)&x[base + 4];
        float4 r0, r1;
        r0.x = acc[i][0] + bi + x0.x; r0.y = acc[i][1] + bi + x0.y;
        r0.z = acc[i][2] + bi + x0.z; r0.w = acc[i][3] + bi + x0.w;
        r1.x = acc[i][4] + bi + x1.x; r1.y = acc[i][5] + bi + x1.y;
        r1.z = acc[i][6] + bi + x1.z; r1.w = acc[i][7] + bi + x1.w;
        *(float4*)&out[base]     = r0;
        *(float4*)&out[base + 4] = r1;
    }
}

// ---------------------------------------------------------------------------
extern "C" void kernel_launch(void* const* d_in, const int* in_sizes, int n_in,
                              void* d_out, int out_size)
{
    (void)in_sizes; (void)n_in; (void)out_size;
    const float* x  = (const float*)d_in[0];
    const float* Wq = (const float*)d_in[1];
    const float* bq = (const float*)d_in[2];
    const float* Wk = (const float*)d_in[3];
    const float* bk = (const float*)d_in[4];
    const float* Wv = (const float*)d_in[5];
    const float* bv = (const float*)d_in[6];
    const float* Wu = (const float*)d_in[7];
    const float* bu = (const float*)d_in[8];
    float* out = (float*)d_out;

    const int ATTN_SMEM = (2 * 64 * QS_STRIDE + 64 * 256 + 64 * PS_STRIDE) * 4; // 216064 B
    cudaFuncSetAttribute(attn_kernel, cudaFuncAttributeMaxDynamicSharedMemorySize, ATTN_SMEM);

    qkv_kernel<<<dim3(32, 4, 12), 256>>>(x, Wq, bq, Wk, bk, Wv, bv);
    attn_kernel<<<dim3(64, 4), 256, ATTN_SMEM>>>();
    out_kernel<<<dim3(32, 4, 4), 256>>>(x, Wu, bu, out);
}

// round 2
// speedup vs baseline: 2.3036x; 2.3036x over previous
#include <cuda_runtime.h>
#include <cuda_bf16.h>
#include <cstdint>

#define BATCH 4
#define CH    256
#define SP    4096   // 64*64 spatial == attention rows
#define DH    256    // head dim == CH

// Scratch (allocation-free rule: __device__ globals)
__device__ __align__(16) __nv_bfloat16 g_qh[BATCH * CH * SP];
__device__ __align__(16) __nv_bfloat16 g_ql[BATCH * CH * SP];
__device__ __align__(16) __nv_bfloat16 g_kh[BATCH * CH * SP];
__device__ __align__(16) __nv_bfloat16 g_kl[BATCH * CH * SP];
__device__ __align__(16) __nv_bfloat16 g_vh[BATCH * CH * SP];
__device__ __align__(16) __nv_bfloat16 g_vl[BATCH * CH * SP];
__device__ __align__(16) float g_a[BATCH * CH * SP];

// ---------------------------------------------------------------------------
// helpers
// ---------------------------------------------------------------------------
__device__ __forceinline__ uint32_t pk(float x0, float x1) {
    // returns packed bf16x2: lower 16 bits = bf16(x0), upper = bf16(x1)
    uint32_t r;
    asm("cvt.rn.bf16x2.f32 %0, %1, %2;" : "=r"(r) : "f"(x1), "f"(x0));
    return r;
}

__device__ __forceinline__ void split2(float x0, float x1, uint32_t& hi, uint32_t& lo) {
    float h0 = __bfloat162float(__float2bfloat16(x0));
    float h1 = __bfloat162float(__float2bfloat16(x1));
    hi = pk(x0, x1);
    lo = pk(x0 - h0, x1 - h1);
}

__device__ __forceinline__ void ldsm4(uint32_t* r, uint32_t a) {
    asm volatile("ldmatrix.sync.aligned.m8n8.x4.shared.b16 {%0,%1,%2,%3}, [%4];"
                 : "=r"(r[0]), "=r"(r[1]), "=r"(r[2]), "=r"(r[3]) : "r"(a));
}
__device__ __forceinline__ void ldsm4t(uint32_t* r, uint32_t a) {
    asm volatile("ldmatrix.sync.aligned.m8n8.x4.trans.shared.b16 {%0,%1,%2,%3}, [%4];"
                 : "=r"(r[0]), "=r"(r[1]), "=r"(r[2]), "=r"(r[3]) : "r"(a));
}
__device__ __forceinline__ void mma16816(float* d, const uint32_t* a, uint32_t b0, uint32_t b1) {
    asm volatile("mma.sync.aligned.m16n8k16.row.col.f32.bf16.bf16.f32 "
                 "{%0,%1,%2,%3}, {%4,%5,%6,%7}, {%8,%9}, {%0,%1,%2,%3};"
                 : "+f"(d[0]), "+f"(d[1]), "+f"(d[2]), "+f"(d[3])
                 : "r"(a[0]), "r"(a[1]), "r"(a[2]), "r"(a[3]), "r"(b0), "r"(b1));
}
__device__ __forceinline__ uint32_t sm_u32(const void* p) {
    return (uint32_t)__cvta_generic_to_shared(p);
}

// ---------------------------------------------------------------------------
// Kernel 1: fused Q/K/V 1x1 conv.  Y[o][s] = b[o] + sum_c W[o][c] x[c][s]
// Emits bf16 hi/lo split outputs for tensor-core attention.
// grid (32 s-tiles, 4 c-tiles, 12 = batch*3 + which), 256 threads
// ---------------------------------------------------------------------------
__global__ __launch_bounds__(256) void qkv_kernel(
    const float* __restrict__ x,
    const float* __restrict__ Wq, const float* __restrict__ bq,
    const float* __restrict__ Wk, const float* __restrict__ bk,
    const float* __restrict__ Wv, const float* __restrict__ bv)
{
    __shared__ float Ws[16][68];    // [k][m], padded
    __shared__ float Xs[16][128];   // [k][n]

    int z = blockIdx.z;
    int b = z / 3, w = z % 3;
    const float* W    = (w == 0) ? Wq : (w == 1) ? Wk : Wv;
    const float* bias = (w == 0) ? bq : (w == 1) ? bk : bv;
    __nv_bfloat16* outh = (w == 0) ? g_qh : (w == 1) ? g_kh : g_vh;
    __nv_bfloat16* outl = (w == 0) ? g_ql : (w == 1) ? g_kl : g_vl;

    int m0 = blockIdx.y * 64;
    int s0 = blockIdx.x * 128;
    int tid = threadIdx.x;
    int ty = tid >> 4, tx = tid & 15;

    float acc[4][8];
#pragma unroll
    for (int i = 0; i < 4; i++)
#pragma unroll
        for (int j = 0; j < 8; j++) acc[i][j] = 0.0f;

    const float* xb = x + (size_t)b * CH * SP;

    for (int k0 = 0; k0 < CH; k0 += 16) {
        {
            int mm = tid & 63, kk4 = (tid >> 6) << 2;
            float4 wv = *(const float4*)&W[(m0 + mm) * CH + k0 + kk4];
            Ws[kk4 + 0][mm] = wv.x;
            Ws[kk4 + 1][mm] = wv.y;
            Ws[kk4 + 2][mm] = wv.z;
            Ws[kk4 + 3][mm] = wv.w;
        }
        {
            int kk = tid >> 4, nn = (tid & 15) * 8;
            const float* xp = xb + (size_t)(k0 + kk) * SP + s0 + nn;
            *(float4*)&Xs[kk][nn]     = *(const float4*)xp;
            *(float4*)&Xs[kk][nn + 4] = *(const float4*)(xp + 4);
        }
        __syncthreads();
#pragma unroll
        for (int k = 0; k < 16; k++) {
            float4 a  = *(const float4*)&Ws[k][ty * 4];
            float4 b0 = *(const float4*)&Xs[k][tx * 8];
            float4 b1 = *(const float4*)&Xs[k][tx * 8 + 4];
            float av[4] = {a.x, a.y, a.z, a.w};
            float bw[8] = {b0.x, b0.y, b0.z, b0.w, b1.x, b1.y, b1.z, b1.w};
#pragma unroll
            for (int i = 0; i < 4; i++)
#pragma unroll
                for (int j = 0; j < 8; j++)
                    acc[i][j] = fmaf(av[i], bw[j], acc[i][j]);
        }
        __syncthreads();
    }

    size_t ob = (size_t)b * CH * SP;
#pragma unroll
    for (int i = 0; i < 4; i++) {
        int m = m0 + ty * 4 + i;
        float bi = bias[m];
        float v[8];
#pragma unroll
        for (int j = 0; j < 8; j++) v[j] = acc[i][j] + bi;
        uint4 hw, lw;
        uint32_t h0, l0, h1, l1, h2, l2, h3, l3;
        split2(v[0], v[1], h0, l0);
        split2(v[2], v[3], h1, l1);
        split2(v[4], v[5], h2, l2);
        split2(v[6], v[7], h3, l3);
        hw.x = h0; hw.y = h1; hw.z = h2; hw.w = h3;
        lw.x = l0; lw.y = l1; lw.z = l2; lw.w = l3;
        size_t off = ob + (size_t)m * SP + s0 + tx * 8;
        *(uint4*)&outh[off] = hw;
        *(uint4*)&outl[off] = lw;
    }
}

// ---------------------------------------------------------------------------
// Kernel 2: flash attention on tensor cores (bf16 hi/lo split, fp32 accum).
// Rows = flat view [4096 x 256] of conv output.
// grid (32 row-tiles of 128, 4 batches), 256 threads = 8 warps.
// Warp w handles rows 16w..16w+15 of the 128-row tile; Bc = 32.
// smem: Qh/Ql [128][264]bf16, Kh/Kl/Vh/Vl [32][264]bf16  = 202752 B
// ---------------------------------------------------------------------------
#define SQ 264            // padded row stride in bf16 elements (33 * 8)
#define ATTN_SMEM ((2 * 128 * SQ + 4 * 32 * SQ) * 2)

__global__ __launch_bounds__(256, 1) void attn_kernel()
{
    extern __shared__ __nv_bfloat16 sm[];
    __nv_bfloat16* Qh = sm;
    __nv_bfloat16* Ql = Qh + 128 * SQ;
    __nv_bfloat16* Kh = Ql + 128 * SQ;
    __nv_bfloat16* Kl = Kh + 32 * SQ;
    __nv_bfloat16* Vh = Kl + 32 * SQ;
    __nv_bfloat16* Vl = Vh + 32 * SQ;

    int b = blockIdx.y;
    int n0 = blockIdx.x * 128;
    int tid = threadIdx.x;
    int w = tid >> 5, lane = tid & 31;

    size_t base = (size_t)b * CH * SP;
    const uint4* Qgh = (const uint4*)(g_qh + base);
    const uint4* Qgl = (const uint4*)(g_ql + base);
    const uint4* Kgh = (const uint4*)(g_kh + base);
    const uint4* Kgl = (const uint4*)(g_kl + base);
    const uint4* Vgh = (const uint4*)(g_vh + base);
    const uint4* Vgl = (const uint4*)(g_vl + base);

    // load Q tile (128 rows x 256 ch, hi+lo)
    for (int idx = tid; idx < 128 * 32; idx += 256) {
        int r = idx >> 5, c = idx & 31;
        ((uint4*)Qh)[r * 33 + c] = Qgh[(size_t)(n0 + r) * 32 + c];
        ((uint4*)Ql)[r * 33 + c] = Qgl[(size_t)(n0 + r) * 32 + c];
    }

    // fragment smem addresses (ldmatrix lane-address pattern)
    int rsel = lane & 15, csel = lane >> 4;
    uint32_t aQh = sm_u32(Qh + (w * 16 + rsel) * SQ + csel * 8);
    uint32_t aQl = aQh + 128 * SQ * 2;
    uint32_t aKh = sm_u32(Kh + rsel * SQ + csel * 8);
    uint32_t aKl = aKh + 32 * SQ * 2;
    uint32_t aVh = sm_u32(Vh + rsel * SQ + csel * 8);
    uint32_t aVl = aVh + 32 * SQ * 2;

    float o[32][4];
#pragma unroll
    for (int i = 0; i < 32; i++)
#pragma unroll
        for (int j = 0; j < 4; j++) o[i][j] = 0.0f;
    float m0r = -1e30f, m1r = -1e30f, l0r = 0.0f, l1r = 0.0f;

    for (int mt = 0; mt < 128; mt++) {
        __syncthreads();
        for (int idx = tid; idx < 1024; idx += 256) {
            int r = idx >> 5, c = idx & 31;
            size_t g = (size_t)(mt * 32 + r) * 32 + c;
            int s = r * 33 + c;
            ((uint4*)Kh)[s] = Kgh[g];
            ((uint4*)Kl)[s] = Kgl[g];
            ((uint4*)Vh)[s] = Vgh[g];
            ((uint4*)Vl)[s] = Vgl[g];
        }
        __syncthreads();

        // ---- S = Q K^T for this warp's 16 rows x 32 cols ----
        float s[4][4];
#pragma unroll
        for (int i = 0; i < 4; i++)
#pragma unroll
            for (int j = 0; j < 4; j++) s[i][j] = 0.0f;

#pragma unroll
        for (int kc = 0; kc < 16; kc++) {
            uint32_t ah[4], al[4];
            ldsm4(ah, aQh + kc * 32);
            ldsm4(al, aQl + kc * 32);
#pragma unroll
            for (int np = 0; np < 2; np++) {
                uint32_t bh[4], bl[4];
                ldsm4(bh, aKh + np * (16 * SQ * 2) + kc * 32);
                ldsm4(bl, aKl + np * (16 * SQ * 2) + kc * 32);
                float* sA = s[2 * np];
                float* sB = s[2 * np + 1];
                mma16816(sA, ah, bh[0], bh[2]);
                mma16816(sA, ah, bl[0], bl[2]);
                mma16816(sA, al, bh[0], bh[2]);
                mma16816(sB, ah, bh[1], bh[3]);
                mma16816(sB, ah, bl[1], bl[3]);
                mma16816(sB, al, bh[1], bh[3]);
            }
        }

        // ---- online softmax (rows lane/4 and lane/4+8) ----
        float mx0 = s[0][0], mx1 = s[0][2];
#pragma unroll
        for (int nt = 0; nt < 4; nt++) {
            mx0 = fmaxf(mx0, fmaxf(s[nt][0], s[nt][1]));
            mx1 = fmaxf(mx1, fmaxf(s[nt][2], s[nt][3]));
        }
        mx0 = fmaxf(mx0, __shfl_xor_sync(0xffffffffu, mx0, 1));
        mx0 = fmaxf(mx0, __shfl_xor_sync(0xffffffffu, mx0, 2));
        mx1 = fmaxf(mx1, __shfl_xor_sync(0xffffffffu, mx1, 1));
        mx1 = fmaxf(mx1, __shfl_xor_sync(0xffffffffu, mx1, 2));

        float mn0 = fmaxf(m0r, mx0), mn1 = fmaxf(m1r, mx1);
        float sc0 = __expf(m0r - mn0), sc1 = __expf(m1r - mn1);
        m0r = mn0; m1r = mn1;

        float rs0 = 0.0f, rs1 = 0.0f;
#pragma unroll
        for (int nt = 0; nt < 4; nt++) {
            s[nt][0] = __expf(s[nt][0] - mn0);
            s[nt][1] = __expf(s[nt][1] - mn0);
            s[nt][2] = __expf(s[nt][2] - mn1);
            s[nt][3] = __expf(s[nt][3] - mn1);
            rs0 += s[nt][0] + s[nt][1];
            rs1 += s[nt][2] + s[nt][3];
        }
        rs0 += __shfl_xor_sync(0xffffffffu, rs0, 1);
        rs0 += __shfl_xor_sync(0xffffffffu, rs0, 2);
        rs1 += __shfl_xor_sync(0xffffffffu, rs1, 1);
        rs1 += __shfl_xor_sync(0xffffffffu, rs1, 2);
        l0r = l0r * sc0 + rs0;
        l1r = l1r * sc1 + rs1;

#pragma unroll
        for (int nt = 0; nt < 32; nt++) {
            o[nt][0] *= sc0; o[nt][1] *= sc0;
            o[nt][2] *= sc1; o[nt][3] *= sc1;
        }

        // P (C-fragments) -> A-fragments, bf16 hi/lo split
        uint32_t ph[2][4], pl[2][4];
#pragma unroll
        for (int kc = 0; kc < 2; kc++) {
            int nt0 = 2 * kc, nt1 = 2 * kc + 1;
            split2(s[nt0][0], s[nt0][1], ph[kc][0], pl[kc][0]);
            split2(s[nt0][2], s[nt0][3], ph[kc][1], pl[kc][1]);
            split2(s[nt1][0], s[nt1][1], ph[kc][2], pl[kc][2]);
            split2(s[nt1][2], s[nt1][3], ph[kc][3], pl[kc][3]);
        }

        // ---- O += P V ----
#pragma unroll
        for (int kc = 0; kc < 2; kc++) {
#pragma unroll
            for (int ct = 0; ct < 16; ct++) {
                uint32_t vh[4], vl[4];
                ldsm4t(vh, aVh + kc * (16 * SQ * 2) + ct * 32);
                ldsm4t(vl, aVl + kc * (16 * SQ * 2) + ct * 32);
                float* oA = o[2 * ct];
                float* oB = o[2 * ct + 1];
                mma16816(oA, ph[kc], vh[0], vh[1]);
                mma16816(oA, ph[kc], vl[0], vl[1]);
                mma16816(oA, pl[kc], vh[0], vh[1]);
                mma16816(oB, ph[kc], vh[2], vh[3]);
                mma16816(oB, ph[kc], vl[2], vl[3]);
                mma16816(oB, pl[kc], vh[2], vh[3]);
            }
        }
    }

    // ---- epilogue: normalize, store fp32 rows to g_a ----
    float inv0 = 1.0f / l0r, inv1 = 1.0f / l1r;
    int r0 = n0 + w * 16 + (lane >> 2);
    int r1 = r0 + 8;
    int cb = (lane & 3) * 2;
    float* A = g_a + base;
#pragma unroll
    for (int nt = 0; nt < 32; nt++) {
        int c = nt * 8 + cb;
        float2 v0 = make_float2(o[nt][0] * inv0, o[nt][1] * inv0);
        float2 v1 = make_float2(o[nt][2] * inv1, o[nt][3] * inv1);
        *(float2*)&A[(size_t)r0 * 256 + c] = v0;
        *(float2*)&A[(size_t)r1 * 256 + c] = v1;
    }
}

// ---------------------------------------------------------------------------
// Kernel 3: out = x + Wu * attn + bu   (attn flat buffer viewed as [CH][SP])
// ---------------------------------------------------------------------------
__global__ __launch_bounds__(256) void out_kernel(
    const float* __restrict__ x, const float* __restrict__ Wu,
    const float* __restrict__ bu, float* __restrict__ out)
{
    __shared__ float Ws[16][68];
    __shared__ float Xs[16][128];

    int b = blockIdx.z;
    int m0 = blockIdx.y * 64;
    int s0 = blockIdx.x * 128;
    int tid = threadIdx.x;
    int ty = tid >> 4, tx = tid & 15;

    float acc[4][8];
#pragma unroll
    for (int i = 0; i < 4; i++)
#pragma unroll
        for (int j = 0; j < 8; j++) acc[i][j] = 0.0f;

    const float* Ab = g_a + (size_t)b * CH * SP;

    for (int k0 = 0; k0 < CH; k0 += 16) {
        {
            int mm = tid & 63, kk4 = (tid >> 6) << 2;
            float4 wv = *(const float4*)&Wu[(m0 + mm) * CH + k0 + kk4];
            Ws[kk4 + 0][mm] = wv.x;
            Ws[kk4 + 1][mm] = wv.y;
            Ws[kk4 + 2][mm] = wv.z;
            Ws[kk4 + 3][mm] = wv.w;
        }
        {
            int kk = tid >> 4, nn = (tid & 15) * 8;
            const float* ap = Ab + (size_t)(k0 + kk) * SP + s0 + nn;
            *(float4*)&Xs[kk][nn]     = *(const float4*)ap;
            *(float4*)&Xs[kk][nn + 4] = *(const float4*)(ap + 4);
        }
        __syncthreads();
#pragma unroll
        for (int k = 0; k < 16; k++) {
            float4 a  = *(const float4*)&Ws[k][ty * 4];
            float4 b0 = *(const float4*)&Xs[k][tx * 8];
            float4 b1 = *(const float4*)&Xs[k][tx * 8 + 4];
            float av[4] = {a.x, a.y, a.z, a.w};
            float bw[8] = {b0.x, b0.y, b0.z, b0.w, b1.x, b1.y, b1.z, b1.w};
#pragma unroll
            for (int i = 0; i < 4; i++)
#pragma unroll
                for (int j = 0; j < 8; j++)
                    acc[i][j] = fmaf(av[i], bw[j], acc[i][j]);
        }
        __syncthreads();
    }

#pragma unroll
    for (int i = 0; i < 4; i++) {
        int m = m0 + ty * 4 + i;
        float bi = bu[m];
        size_t bo = (size_t)b * CH * SP + (size_t)m * SP + s0 + tx * 8;
        float4 x0 = *(const float4*)&x[bo];
        float4 x1 = *(const float4*)&x[bo + 4];
        float4 r0, r1;
        r0.x = acc[i][0] + bi + x0.x; r0.y = acc[i][1] + bi + x0.y;
        r0.z = acc[i][2] + bi + x0.z; r0.w = acc[i][3] + bi + x0.w;
        r1.x = acc[i][4] + bi + x1.x; r1.y = acc[i][5] + bi + x1.y;
        r1.z = acc[i][6] + bi + x1.z; r1.w = acc[i][7] + bi + x1.w;
        *(float4*)&out[bo]     = r0;
        *(float4*)&out[bo + 4] = r1;
    }
}

// ---------------------------------------------------------------------------
extern "C" void kernel_launch(void* const* d_in, const int* in_sizes, int n_in,
                              void* d_out, int out_size)
{
    (void)in_sizes; (void)n_in; (void)out_size;
    const float* x  = (const float*)d_in[0];
    const float* Wq = (const float*)d_in[1];
    const float* bq = (const float*)d_in[2];
    const float* Wk = (const float*)d_in[3];
    const float* bk = (const float*)d_in[4];
    const float* Wv = (const float*)d_in[5];
    const float* bv = (const float*)d_in[6];
    const float* Wu = (const float*)d_in[7];
    const float* bu = (const float*)d_in[8];
    float* out = (float*)d_out;

    cudaFuncSetAttribute(attn_kernel, cudaFuncAttributeMaxDynamicSharedMemorySize, ATTN_SMEM);

    qkv_kernel<<<dim3(32, 4, 12), 256>>>(x, Wq, bq, Wk, bk, Wv, bv);
    attn_kernel<<<dim3(32, 4), 256, ATTN_SMEM>>>();
    out_kernel<<<dim3(32, 4, 4), 256>>>(x, Wu, bu, out);
}

// round 3
// speedup vs baseline: 2.3077x; 1.0018x over previous
#include <cuda_runtime.h>
#include <cuda_bf16.h>
#include <cstdint>

#define BATCH 4
#define CH    256
#define SP    4096   // 64*64 spatial == attention rows
#define DH    256    // head dim == CH

// Scratch (allocation-free rule: __device__ globals)
__device__ __align__(16) __nv_bfloat16 g_qh[BATCH * CH * SP];
__device__ __align__(16) __nv_bfloat16 g_ql[BATCH * CH * SP];
__device__ __align__(16) __nv_bfloat16 g_kh[BATCH * CH * SP];
__device__ __align__(16) __nv_bfloat16 g_kl[BATCH * CH * SP];
__device__ __align__(16) __nv_bfloat16 g_vh[BATCH * CH * SP];
__device__ __align__(16) __nv_bfloat16 g_vl[BATCH * CH * SP];
__device__ __align__(16) float g_a[BATCH * CH * SP];

// ---------------------------------------------------------------------------
// helpers
// ---------------------------------------------------------------------------
__device__ __forceinline__ uint32_t pk(float x0, float x1) {
    // returns packed bf16x2: lower 16 bits = bf16(x0), upper = bf16(x1)
    uint32_t r;
    asm("cvt.rn.bf16x2.f32 %0, %1, %2;" : "=r"(r) : "f"(x1), "f"(x0));
    return r;
}

__device__ __forceinline__ void split2(float x0, float x1, uint32_t& hi, uint32_t& lo) {
    float h0 = __bfloat162float(__float2bfloat16(x0));
    float h1 = __bfloat162float(__float2bfloat16(x1));
    hi = pk(x0, x1);
    lo = pk(x0 - h0, x1 - h1);
}

__device__ __forceinline__ void ldsm4(uint32_t* r, uint32_t a) {
    asm volatile("ldmatrix.sync.aligned.m8n8.x4.shared.b16 {%0,%1,%2,%3}, [%4];"
                 : "=r"(r[0]), "=r"(r[1]), "=r"(r[2]), "=r"(r[3]) : "r"(a));
}
__device__ __forceinline__ void ldsm4t(uint32_t* r, uint32_t a) {
    asm volatile("ldmatrix.sync.aligned.m8n8.x4.trans.shared.b16 {%0,%1,%2,%3}, [%4];"
                 : "=r"(r[0]), "=r"(r[1]), "=r"(r[2]), "=r"(r[3]) : "r"(a));
}
__device__ __forceinline__ void mma16816(float* d, const uint32_t* a, uint32_t b0, uint32_t b1) {
    asm volatile("mma.sync.aligned.m16n8k16.row.col.f32.bf16.bf16.f32 "
                 "{%0,%1,%2,%3}, {%4,%5,%6,%7}, {%8,%9}, {%0,%1,%2,%3};"
                 : "+f"(d[0]), "+f"(d[1]), "+f"(d[2]), "+f"(d[3])
                 : "r"(a[0]), "r"(a[1]), "r"(a[2]), "r"(a[3]), "r"(b0), "r"(b1));
}
__device__ __forceinline__ uint32_t sm_u32(const void* p) {
    return (uint32_t)__cvta_generic_to_shared(p);
}

// ---------------------------------------------------------------------------
// Kernel 1: fused Q/K/V 1x1 conv.  Y[o][s] = b[o] + sum_c W[o][c] x[c][s]
// Emits bf16 hi/lo split outputs for tensor-core attention.
// grid (32 s-tiles, 4 c-tiles, 12 = batch*3 + which), 256 threads
// ---------------------------------------------------------------------------
__global__ __launch_bounds__(256) void qkv_kernel(
    const float* __restrict__ x,
    const float* __restrict__ Wq, const float* __restrict__ bq,
    const float* __restrict__ Wk, const float* __restrict__ bk,
    const float* __restrict__ Wv, const float* __restrict__ bv)
{
    __shared__ float Ws[16][68];    // [k][m], padded
    __shared__ float Xs[16][128];   // [k][n]

    int z = blockIdx.z;
    int b = z / 3, w = z % 3;
    const float* W    = (w == 0) ? Wq : (w == 1) ? Wk : Wv;
    const float* bias = (w == 0) ? bq : (w == 1) ? bk : bv;
    __nv_bfloat16* outh = (w == 0) ? g_qh : (w == 1) ? g_kh : g_vh;
    __nv_bfloat16* outl = (w == 0) ? g_ql : (w == 1) ? g_kl : g_vl;

    int m0 = blockIdx.y * 64;
    int s0 = blockIdx.x * 128;
    int tid = threadIdx.x;
    int ty = tid >> 4, tx = tid & 15;

    float acc[4][8];
#pragma unroll
    for (int i = 0; i < 4; i++)
#pragma unroll
        for (int j = 0; j < 8; j++) acc[i][j] = 0.0f;

    const float* xb = x + (size_t)b * CH * SP;

    for (int k0 = 0; k0 < CH; k0 += 16) {
        {
            int mm = tid & 63, kk4 = (tid >> 6) << 2;
            float4 wv = *(const float4*)&W[(m0 + mm) * CH + k0 + kk4];
            Ws[kk4 + 0][mm] = wv.x;
            Ws[kk4 + 1][mm] = wv.y;
            Ws[kk4 + 2][mm] = wv.z;
            Ws[kk4 + 3][mm] = wv.w;
        }
        {
            int kk = tid >> 4, nn = (tid & 15) * 8;
            const float* xp = xb + (size_t)(k0 + kk) * SP + s0 + nn;
            *(float4*)&Xs[kk][nn]     = *(const float4*)xp;
            *(float4*)&Xs[kk][nn + 4] = *(const float4*)(xp + 4);
        }
        __syncthreads();
#pragma unroll
        for (int k = 0; k < 16; k++) {
            float4 a  = *(const float4*)&Ws[k][ty * 4];
            float4 b0 = *(const float4*)&Xs[k][tx * 8];
            float4 b1 = *(const float4*)&Xs[k][tx * 8 + 4];
            float av[4] = {a.x, a.y, a.z, a.w};
            float bw[8] = {b0.x, b0.y, b0.z, b0.w, b1.x, b1.y, b1.z, b1.w};
#pragma unroll
            for (int i = 0; i < 4; i++)
#pragma unroll
                for (int j = 0; j < 8; j++)
                    acc[i][j] = fmaf(av[i], bw[j], acc[i][j]);
        }
        __syncthreads();
    }

    size_t ob = (size_t)b * CH * SP;
#pragma unroll
    for (int i = 0; i < 4; i++) {
        int m = m0 + ty * 4 + i;
        float bi = bias[m];
        float v[8];
#pragma unroll
        for (int j = 0; j < 8; j++) v[j] = acc[i][j] + bi;
        uint4 hw, lw;
        uint32_t h0, l0, h1, l1, h2, l2, h3, l3;
        split2(v[0], v[1], h0, l0);
        split2(v[2], v[3], h1, l1);
        split2(v[4], v[5], h2, l2);
        split2(v[6], v[7], h3, l3);
        hw.x = h0; hw.y = h1; hw.z = h2; hw.w = h3;
        lw.x = l0; lw.y = l1; lw.z = l2; lw.w = l3;
        size_t off = ob + (size_t)m * SP + s0 + tx * 8;
        *(uint4*)&outh[off] = hw;
        *(uint4*)&outl[off] = lw;
    }
}

// ---------------------------------------------------------------------------
// Kernel 2: flash attention on tensor cores (bf16 hi/lo split, fp32 accum).
// Rows = flat view [4096 x 256] of conv output.
// grid (32 row-tiles of 128, 4 batches), 256 threads = 8 warps.
// Warp w handles rows 16w..16w+15 of the 128-row tile; Bc = 32.
// smem: Qh/Ql [128][264]bf16, Kh/Kl/Vh/Vl [32][264]bf16  = 202752 B
// ---------------------------------------------------------------------------
#define SQ 264            // padded row stride in bf16 elements (33 * 8)
#define ATTN_SMEM ((2 * 128 * SQ + 4 * 32 * SQ) * 2)

__global__ __launch_bounds__(256, 1) void attn_kernel()
{
    extern __shared__ __nv_bfloat16 sm[];
    __nv_bfloat16* Qh = sm;
    __nv_bfloat16* Ql = Qh + 128 * SQ;
    __nv_bfloat16* Kh = Ql + 128 * SQ;
    __nv_bfloat16* Kl = Kh + 32 * SQ;
    __nv_bfloat16* Vh = Kl + 32 * SQ;
    __nv_bfloat16* Vl = Vh + 32 * SQ;

    int b = blockIdx.y;
    int n0 = blockIdx.x * 128;
    int tid = threadIdx.x;
    int w = tid >> 5, lane = tid & 31;

    size_t base = (size_t)b * CH * SP;
    const uint4* Qgh = (const uint4*)(g_qh + base);
    const uint4* Qgl = (const uint4*)(g_ql + base);
    const uint4* Kgh = (const uint4*)(g_kh + base);
    const uint4* Kgl = (const uint4*)(g_kl + base);
    const uint4* Vgh = (const uint4*)(g_vh + base);
    const uint4* Vgl = (const uint4*)(g_vl + base);

    // load Q tile (128 rows x 256 ch, hi+lo)
    for (int idx = tid; idx < 128 * 32; idx += 256) {
        int r = idx >> 5, c = idx & 31;
        ((uint4*)Qh)[r * 33 + c] = Qgh[(size_t)(n0 + r) * 32 + c];
        ((uint4*)Ql)[r * 33 + c] = Qgl[(size_t)(n0 + r) * 32 + c];
    }

    // fragment smem addresses (ldmatrix lane-address pattern)
    int rsel = lane & 15, csel = lane >> 4;
    uint32_t aQh = sm_u32(Qh + (w * 16 + rsel) * SQ + csel * 8);
    uint32_t aQl = aQh + 128 * SQ * 2;
    uint32_t aKh = sm_u32(Kh + rsel * SQ + csel * 8);
    uint32_t aKl = aKh + 32 * SQ * 2;
    uint32_t aVh = sm_u32(Vh + rsel * SQ + csel * 8);
    uint32_t aVl = aVh + 32 * SQ * 2;

    float o[32][4];
#pragma unroll
    for (int i = 0; i < 32; i++)
#pragma unroll
        for (int j = 0; j < 4; j++) o[i][j] = 0.0f;
    float m0r = -1e30f, m1r = -1e30f, l0r = 0.0f, l1r = 0.0f;

    for (int mt = 0; mt < 128; mt++) {
        __syncthreads();
        for (int idx = tid; idx < 1024; idx += 256) {
            int r = idx >> 5, c = idx & 31;
            size_t g = (size_t)(mt * 32 + r) * 32 + c;
            int s = r * 33 + c;
            ((uint4*)Kh)[s] = Kgh[g];
            ((uint4*)Kl)[s] = Kgl[g];
            ((uint4*)Vh)[s] = Vgh[g];
            ((uint4*)Vl)[s] = Vgl[g];
        }
        __syncthreads();

        // ---- S = Q K^T for this warp's 16 rows x 32 cols ----
        float s[4][4];
#pragma unroll
        for (int i = 0; i < 4; i++)
#pragma unroll
            for (int j = 0; j < 4; j++) s[i][j] = 0.0f;

#pragma unroll
        for (int kc = 0; kc < 16; kc++) {
            uint32_t ah[4], al[4];
            ldsm4(ah, aQh + kc * 32);
            ldsm4(al, aQl + kc * 32);
#pragma unroll
            for (int np = 0; np < 2; np++) {
                uint32_t bh[4], bl[4];
                ldsm4(bh, aKh + np * (16 * SQ * 2) + kc * 32);
                ldsm4(bl, aKl + np * (16 * SQ * 2) + kc * 32);
                float* sA = s[2 * np];
                float* sB = s[2 * np + 1];
                mma16816(sA, ah, bh[0], bh[2]);
                mma16816(sA, ah, bl[0], bl[2]);
                mma16816(sA, al, bh[0], bh[2]);
                mma16816(sB, ah, bh[1], bh[3]);
                mma16816(sB, ah, bl[1], bl[3]);
                mma16816(sB, al, bh[1], bh[3]);
            }
        }

        // ---- online softmax (rows lane/4 and lane/4+8) ----
        float mx0 = s[0][0], mx1 = s[0][2];
#pragma unroll
        for (int nt = 0; nt < 4; nt++) {
            mx0 = fmaxf(mx0, fmaxf(s[nt][0], s[nt][1]));
            mx1 = fmaxf(mx1, fmaxf(s[nt][2], s[nt][3]));
        }
        mx0 = fmaxf(mx0, __shfl_xor_sync(0xffffffffu, mx0, 1));
        mx0 = fmaxf(mx0, __shfl_xor_sync(0xffffffffu, mx0, 2));
        mx1 = fmaxf(mx1, __shfl_xor_sync(0xffffffffu, mx1, 1));
        mx1 = fmaxf(mx1, __shfl_xor_sync(0xffffffffu, mx1, 2));

        float mn0 = fmaxf(m0r, mx0), mn1 = fmaxf(m1r, mx1);
        float sc0 = __expf(m0r - mn0), sc1 = __expf(m1r - mn1);
        m0r = mn0; m1r = mn1;

        float rs0 = 0.0f, rs1 = 0.0f;
#pragma unroll
        for (int nt = 0; nt < 4; nt++) {
            s[nt][0] = __expf(s[nt][0] - mn0);
            s[nt][1] = __expf(s[nt][1] - mn0);
            s[nt][2] = __expf(s[nt][2] - mn1);
            s[nt][3] = __expf(s[nt][3] - mn1);
            rs0 += s[nt][0] + s[nt][1];
            rs1 += s[nt][2] + s[nt][3];
        }
        rs0 += __shfl_xor_sync(0xffffffffu, rs0, 1);
        rs0 += __shfl_xor_sync(0xffffffffu, rs0, 2);
        rs1 += __shfl_xor_sync(0xffffffffu, rs1, 1);
        rs1 += __shfl_xor_sync(0xffffffffu, rs1, 2);
        l0r = l0r * sc0 + rs0;
        l1r = l1r * sc1 + rs1;

#pragma unroll
        for (int nt = 0; nt < 32; nt++) {
            o[nt][0] *= sc0; o[nt][1] *= sc0;
            o[nt][2] *= sc1; o[nt][3] *= sc1;
        }

        // P (C-fragments) -> A-fragments, bf16 hi/lo split
        uint32_t ph[2][4], pl[2][4];
#pragma unroll
        for (int kc = 0; kc < 2; kc++) {
            int nt0 = 2 * kc, nt1 = 2 * kc + 1;
            split2(s[nt0][0], s[nt0][1], ph[kc][0], pl[kc][0]);
            split2(s[nt0][2], s[nt0][3], ph[kc][1], pl[kc][1]);
            split2(s[nt1][0], s[nt1][1], ph[kc][2], pl[kc][2]);
            split2(s[nt1][2], s[nt1][3], ph[kc][3], pl[kc][3]);
        }

        // ---- O += P V ----
#pragma unroll
        for (int kc = 0; kc < 2; kc++) {
#pragma unroll
            for (int ct = 0; ct < 16; ct++) {
                uint32_t vh[4], vl[4];
                ldsm4t(vh, aVh + kc * (16 * SQ * 2) + ct * 32);
                ldsm4t(vl, aVl + kc * (16 * SQ * 2) + ct * 32);
                float* oA = o[2 * ct];
                float* oB = o[2 * ct + 1];
                mma16816(oA, ph[kc], vh[0], vh[1]);
                mma16816(oA, ph[kc], vl[0], vl[1]);
                mma16816(oA, pl[kc], vh[0], vh[1]);
                mma16816(oB, ph[kc], vh[2], vh[3]);
                mma16816(oB, ph[kc], vl[2], vl[3]);
                mma16816(oB, pl[kc], vh[2], vh[3]);
            }
        }
    }

    // ---- epilogue: normalize, store fp32 rows to g_a ----
    float inv0 = 1.0f / l0r, inv1 = 1.0f / l1r;
    int r0 = n0 + w * 16 + (lane >> 2);
    int r1 = r0 + 8;
    int cb = (lane & 3) * 2;
    float* A = g_a + base;
#pragma unroll
    for (int nt = 0; nt < 32; nt++) {
        int c = nt * 8 + cb;
        float2 v0 = make_float2(o[nt][0] * inv0, o[nt][1] * inv0);
        float2 v1 = make_float2(o[nt][2] * inv1, o[nt][3] * inv1);
        *(float2*)&A[(size_t)r0 * 256 + c] = v0;
        *(float2*)&A[(size_t)r1 * 256 + c] = v1;
    }
}

// ---------------------------------------------------------------------------
// Kernel 3: out = x + Wu * attn + bu   (attn flat buffer viewed as [CH][SP])
// ---------------------------------------------------------------------------
__global__ __launch_bounds__(256) void out_kernel(
    const float* __restrict__ x, const float* __restrict__ Wu,
    const float* __restrict__ bu, float* __restrict__ out)
{
    __shared__ float Ws[16][68];
    __shared__ float Xs[16][128];

    int b = blockIdx.z;
    int m0 = blockIdx.y * 64;
    int s0 = blockIdx.x * 128;
    int tid = threadIdx.x;
    int ty = tid >> 4, tx = tid & 15;

    float acc[4][8];
#pragma unroll
    for (int i = 0; i < 4; i++)
#pragma unroll
        for (int j = 0; j < 8; j++) acc[i][j] = 0.0f;

    const float* Ab = g_a + (size_t)b * CH * SP;

    for (int k0 = 0; k0 < CH; k0 += 16) {
        {
            int mm = tid & 63, kk4 = (tid >> 6) << 2;
            float4 wv = *(const float4*)&Wu[(m0 + mm) * CH + k0 + kk4];
            Ws[kk4 + 0][mm] = wv.x;
            Ws[kk4 + 1][mm] = wv.y;
            Ws[kk4 + 2][mm] = wv.z;
            Ws[kk4 + 3][mm] = wv.w;
        }
        {
            int kk = tid >> 4, nn = (tid & 15) * 8;
            const float* ap = Ab + (size_t)(k0 + kk) * SP + s0 + nn;
            *(float4*)&Xs[kk][nn]     = *(const float4*)ap;
            *(float4*)&Xs[kk][nn + 4] = *(const float4*)(ap + 4);
        }
        __syncthreads();
#pragma unroll
        for (int k = 0; k < 16; k++) {
            float4 a  = *(const float4*)&Ws[k][ty * 4];
            float4 b0 = *(const float4*)&Xs[k][tx * 8];
            float4 b1 = *(const float4*)&Xs[k][tx * 8 + 4];
            float av[4] = {a.x, a.y, a.z, a.w};
            float bw[8] = {b0.x, b0.y, b0.z, b0.w, b1.x, b1.y, b1.z, b1.w};
#pragma unroll
            for (int i = 0; i < 4; i++)
#pragma unroll
                for (int j = 0; j < 8; j++)
                    acc[i][j] = fmaf(av[i], bw[j], acc[i][j]);
        }
        __syncthreads();
    }

#pragma unroll
    for (int i = 0; i < 4; i++) {
        int m = m0 + ty * 4 + i;
        float bi = bu[m];
        size_t bo = (size_t)b * CH * SP + (size_t)m * SP + s0 + tx * 8;
        float4 x0 = *(const float4*)&x[bo];
        float4 x1 = *(const float4*)&x[bo + 4];
        float4 r0, r1;
        r0.x = acc[i][0] + bi + x0.x; r0.y = acc[i][1] + bi + x0.y;
        r0.z = acc[i][2] + bi + x0.z; r0.w = acc[i][3] + bi + x0.w;
        r1.x = acc[i][4] + bi + x1.x; r1.y = acc[i][5] + bi + x1.y;
        r1.z = acc[i][6] + bi + x1.z; r1.w = acc[i][7] + bi + x1.w;
        *(float4*)&out[bo]     = r0;
        *(float4*)&out[bo + 4] = r1;
    }
}

// ---------------------------------------------------------------------------
extern "C" void kernel_launch(void* const* d_in, const int* in_sizes, int n_in,
                              void* d_out, int out_size)
{
    (void)in_sizes; (void)n_in; (void)out_size;
    const float* x  = (const float*)d_in[0];
    const float* Wq = (const float*)d_in[1];
    const float* bq = (const float*)d_in[2];
    const float* Wk = (const float*)d_in[3];
    const float* bk = (const float*)d_in[4];
    const float* Wv = (const float*)d_in[5];
    const float* bv = (const float*)d_in[6];
    const float* Wu = (const float*)d_in[7];
    const float* bu = (const float*)d_in[8];
    float* out = (float*)d_out;

    cudaFuncSetAttribute(attn_kernel, cudaFuncAttributeMaxDynamicSharedMemorySize, ATTN_SMEM);

    qkv_kernel<<<dim3(32, 4, 12), 256>>>(x, Wq, bq, Wk, bk, Wv, bv);
    attn_kernel<<<dim3(32, 4), 256, ATTN_SMEM>>>();
    out_kernel<<<dim3(32, 4, 4), 256>>>(x, Wu, bu, out);
}

// round 4
// speedup vs baseline: 2.3677x; 1.0260x over previous
#include <cuda_runtime.h>
#include <cuda_bf16.h>
#include <cstdint>

#define BATCH 4
#define CH    256
#define SP    4096   // 64*64 spatial == attention rows
#define DH    256    // head dim == CH

// Scratch (allocation-free rule: __device__ globals)
__device__ __align__(16) __nv_bfloat16 g_qh[BATCH * CH * SP];
__device__ __align__(16) __nv_bfloat16 g_ql[BATCH * CH * SP];
__device__ __align__(16) __nv_bfloat16 g_kh[BATCH * CH * SP];
__device__ __align__(16) __nv_bfloat16 g_kl[BATCH * CH * SP];
__device__ __align__(16) __nv_bfloat16 g_vh[BATCH * CH * SP];
__device__ __align__(16) __nv_bfloat16 g_vl[BATCH * CH * SP];
__device__ __align__(16) float g_a[BATCH * CH * SP];

// ---------------------------------------------------------------------------
// helpers
// ---------------------------------------------------------------------------
__device__ __forceinline__ uint32_t pk(float x0, float x1) {
    uint32_t r;
    asm("cvt.rn.bf16x2.f32 %0, %1, %2;" : "=r"(r) : "f"(x1), "f"(x0));
    return r;
}

__device__ __forceinline__ void split2(float x0, float x1, uint32_t& hi, uint32_t& lo) {
    float h0 = __bfloat162float(__float2bfloat16(x0));
    float h1 = __bfloat162float(__float2bfloat16(x1));
    hi = pk(x0, x1);
    lo = pk(x0 - h0, x1 - h1);
}

__device__ __forceinline__ void ldsm4(uint32_t* r, uint32_t a) {
    asm volatile("ldmatrix.sync.aligned.m8n8.x4.shared.b16 {%0,%1,%2,%3}, [%4];"
                 : "=r"(r[0]), "=r"(r[1]), "=r"(r[2]), "=r"(r[3]) : "r"(a));
}
__device__ __forceinline__ void ldsm4t(uint32_t* r, uint32_t a) {
    asm volatile("ldmatrix.sync.aligned.m8n8.x4.trans.shared.b16 {%0,%1,%2,%3}, [%4];"
                 : "=r"(r[0]), "=r"(r[1]), "=r"(r[2]), "=r"(r[3]) : "r"(a));
}
__device__ __forceinline__ void mma16816(float* d, const uint32_t* a, uint32_t b0, uint32_t b1) {
    asm volatile("mma.sync.aligned.m16n8k16.row.col.f32.bf16.bf16.f32 "
                 "{%0,%1,%2,%3}, {%4,%5,%6,%7}, {%8,%9}, {%0,%1,%2,%3};"
                 : "+f"(d[0]), "+f"(d[1]), "+f"(d[2]), "+f"(d[3])
                 : "r"(a[0]), "r"(a[1]), "r"(a[2]), "r"(a[3]), "r"(b0), "r"(b1));
}
__device__ __forceinline__ uint32_t sm_u32(const void* p) {
    return (uint32_t)__cvta_generic_to_shared(p);
}
__device__ __forceinline__ void cpa16(uint32_t dst, const void* src) {
    asm volatile("cp.async.cg.shared.global [%0], [%1], 16;" :: "r"(dst), "l"(src));
}
__device__ __forceinline__ void cpa_commit() {
    asm volatile("cp.async.commit_group;");
}
__device__ __forceinline__ void cpa_wait_all() {
    asm volatile("cp.async.wait_group 0;");
}

// ---------------------------------------------------------------------------
// Kernel 1: fused Q/K/V 1x1 conv -> bf16 hi/lo outputs.
// grid (32 s-tiles, 4 c-tiles, 12 = batch*3 + which), 256 threads
// ---------------------------------------------------------------------------
__global__ __launch_bounds__(256) void qkv_kernel(
    const float* __restrict__ x,
    const float* __restrict__ Wq, const float* __restrict__ bq,
    const float* __restrict__ Wk, const float* __restrict__ bk,
    const float* __restrict__ Wv, const float* __restrict__ bv)
{
    __shared__ float Ws[16][68];
    __shared__ float Xs[16][128];

    int z = blockIdx.z;
    int b = z / 3, w = z % 3;
    const float* W    = (w == 0) ? Wq : (w == 1) ? Wk : Wv;
    const float* bias = (w == 0) ? bq : (w == 1) ? bk : bv;
    __nv_bfloat16* outh = (w == 0) ? g_qh : (w == 1) ? g_kh : g_vh;
    __nv_bfloat16* outl = (w == 0) ? g_ql : (w == 1) ? g_kl : g_vl;

    int m0 = blockIdx.y * 64;
    int s0 = blockIdx.x * 128;
    int tid = threadIdx.x;
    int ty = tid >> 4, tx = tid & 15;

    float acc[4][8];
#pragma unroll
    for (int i = 0; i < 4; i++)
#pragma unroll
        for (int j = 0; j < 8; j++) acc[i][j] = 0.0f;

    const float* xb = x + (size_t)b * CH * SP;

    for (int k0 = 0; k0 < CH; k0 += 16) {
        {
            int mm = tid & 63, kk4 = (tid >> 6) << 2;
            float4 wv = *(const float4*)&W[(m0 + mm) * CH + k0 + kk4];
            Ws[kk4 + 0][mm] = wv.x;
            Ws[kk4 + 1][mm] = wv.y;
            Ws[kk4 + 2][mm] = wv.z;
            Ws[kk4 + 3][mm] = wv.w;
        }
        {
            int kk = tid >> 4, nn = (tid & 15) * 8;
            const float* xp = xb + (size_t)(k0 + kk) * SP + s0 + nn;
            *(float4*)&Xs[kk][nn]     = *(const float4*)xp;
            *(float4*)&Xs[kk][nn + 4] = *(const float4*)(xp + 4);
        }
        __syncthreads();
#pragma unroll
        for (int k = 0; k < 16; k++) {
            float4 a  = *(const float4*)&Ws[k][ty * 4];
            float4 b0 = *(const float4*)&Xs[k][tx * 8];
            float4 b1 = *(const float4*)&Xs[k][tx * 8 + 4];
            float av[4] = {a.x, a.y, a.z, a.w};
            float bw[8] = {b0.x, b0.y, b0.z, b0.w, b1.x, b1.y, b1.z, b1.w};
#pragma unroll
            for (int i = 0; i < 4; i++)
#pragma unroll
                for (int j = 0; j < 8; j++)
                    acc[i][j] = fmaf(av[i], bw[j], acc[i][j]);
        }
        __syncthreads();
    }

    size_t ob = (size_t)b * CH * SP;
#pragma unroll
    for (int i = 0; i < 4; i++) {
        int m = m0 + ty * 4 + i;
        float bi = bias[m];
        float v[8];
#pragma unroll
        for (int j = 0; j < 8; j++) v[j] = acc[i][j] + bi;
        uint4 hw, lw;
        split2(v[0], v[1], hw.x, lw.x);
        split2(v[2], v[3], hw.y, lw.y);
        split2(v[4], v[5], hw.z, lw.z);
        split2(v[6], v[7], hw.w, lw.w);
        size_t off = ob + (size_t)m * SP + s0 + tx * 8;
        *(uint4*)&outh[off] = hw;
        *(uint4*)&outl[off] = lw;
    }
}

// ---------------------------------------------------------------------------
// Kernel 2: flash attention, tensor cores, cp.async pipelined K/V tiles.
// grid (32 row-tiles of 128, 4 batches), 256 threads = 8 warps.
// ---------------------------------------------------------------------------
#define SQ 264            // padded row stride in bf16 (33 * 8)
#define ATTN_SMEM ((2 * 128 * SQ + 4 * 32 * SQ) * 2)

__global__ __launch_bounds__(256, 1) void attn_kernel()
{
    extern __shared__ __nv_bfloat16 sm[];
    __nv_bfloat16* Qh = sm;
    __nv_bfloat16* Ql = Qh + 128 * SQ;
    __nv_bfloat16* Kh = Ql + 128 * SQ;
    __nv_bfloat16* Kl = Kh + 32 * SQ;
    __nv_bfloat16* Vh = Kl + 32 * SQ;
    __nv_bfloat16* Vl = Vh + 32 * SQ;

    int b = blockIdx.y;
    int n0 = blockIdx.x * 128;
    int tid = threadIdx.x;
    int w = tid >> 5, lane = tid & 31;

    size_t base = (size_t)b * CH * SP;
    const uint4* Qgh = (const uint4*)(g_qh + base);
    const uint4* Qgl = (const uint4*)(g_ql + base);
    const uint4* Kgh = (const uint4*)(g_kh + base);
    const uint4* Kgl = (const uint4*)(g_kl + base);
    const uint4* Vgh = (const uint4*)(g_vh + base);
    const uint4* Vgl = (const uint4*)(g_vl + base);

    // this thread's 4 slots per 32x32-uint4 tile load (1024 uint4 / 256 thr)
    int lr0 = tid >> 3, lc0 = (tid & 7) * 4;   // rows 0..31, 4 consecutive uint4

    uint32_t sKh = sm_u32(Kh), sKl = sm_u32(Kl), sVh = sm_u32(Vh), sVl = sm_u32(Vl);

    // ---- issue K_0 ----
    {
        size_t g = (size_t)lr0 * 32 + lc0;
        uint32_t s = (uint32_t)(lr0 * 33 + lc0) * 16;
#pragma unroll
        for (int j = 0; j < 4; j++) {
            cpa16(sKh + s + j * 16, Kgh + g + j);
            cpa16(sKl + s + j * 16, Kgl + g + j);
        }
        cpa_commit();
    }

    // load Q tile (128 rows x 256 ch, hi+lo) with plain loads (overlaps K_0)
    for (int idx = tid; idx < 128 * 32; idx += 256) {
        int r = idx >> 5, c = idx & 31;
        ((uint4*)Qh)[r * 33 + c] = Qgh[(size_t)(n0 + r) * 32 + c];
        ((uint4*)Ql)[r * 33 + c] = Qgl[(size_t)(n0 + r) * 32 + c];
    }

    // fragment smem addresses (ldmatrix lane-address pattern)
    int rsel = lane & 15, csel = lane >> 4;
    uint32_t aQh = sm_u32(Qh + (w * 16 + rsel) * SQ + csel * 8);
    uint32_t aQl = aQh + 128 * SQ * 2;
    uint32_t aKh = sm_u32(Kh + rsel * SQ + csel * 8);
    uint32_t aKl = aKh + 32 * SQ * 2;
    uint32_t aVh = sm_u32(Vh + rsel * SQ + csel * 8);
    uint32_t aVl = aVh + 32 * SQ * 2;

    float o[32][4];
#pragma unroll
    for (int i = 0; i < 32; i++)
#pragma unroll
        for (int j = 0; j < 4; j++) o[i][j] = 0.0f;
    float m0r = -1e30f, m1r = -1e30f, l0r = 0.0f, l1r = 0.0f;

    for (int mt = 0; mt < 128; mt++) {
        // ---- K_mt ready; all warps past PV_{mt-1} ----
        cpa_wait_all();
        __syncthreads();

        // issue V_mt (overlaps S compute)
        {
            size_t g = (size_t)(mt * 32 + lr0) * 32 + lc0;
            uint32_t s = (uint32_t)(lr0 * 33 + lc0) * 16;
#pragma unroll
            for (int j = 0; j < 4; j++) {
                cpa16(sVh + s + j * 16, Vgh + g + j);
                cpa16(sVl + s + j * 16, Vgl + g + j);
            }
            cpa_commit();
        }

        // ---- S = Q K^T for this warp's 16 rows x 32 cols ----
        float s[4][4];
#pragma unroll
        for (int i = 0; i < 4; i++)
#pragma unroll
            for (int j = 0; j < 4; j++) s[i][j] = 0.0f;

#pragma unroll
        for (int kc = 0; kc < 16; kc++) {
            uint32_t ah[4], al[4];
            ldsm4(ah, aQh + kc * 32);
            ldsm4(al, aQl + kc * 32);
#pragma unroll
            for (int np = 0; np < 2; np++) {
                uint32_t bh[4], bl[4];
                ldsm4(bh, aKh + np * (16 * SQ * 2) + kc * 32);
                ldsm4(bl, aKl + np * (16 * SQ * 2) + kc * 32);
                float* sA = s[2 * np];
                float* sB = s[2 * np + 1];
                mma16816(sA, ah, bh[0], bh[2]);
                mma16816(sA, ah, bl[0], bl[2]);
                mma16816(sA, al, bh[0], bh[2]);
                mma16816(sB, ah, bh[1], bh[3]);
                mma16816(sB, ah, bl[1], bl[3]);
                mma16816(sB, al, bh[1], bh[3]);
            }
        }

        // ---- V_mt ready; all warps past S_mt (K buffer free) ----
        cpa_wait_all();
        __syncthreads();

        // issue K_{mt+1} (overlaps softmax + PV)
        if (mt + 1 < 128) {
            size_t g = (size_t)((mt + 1) * 32 + lr0) * 32 + lc0;
            uint32_t s2 = (uint32_t)(lr0 * 33 + lc0) * 16;
#pragma unroll
            for (int j = 0; j < 4; j++) {
                cpa16(sKh + s2 + j * 16, Kgh + g + j);
                cpa16(sKl + s2 + j * 16, Kgl + g + j);
            }
            cpa_commit();
        }

        // ---- online softmax (rows lane/4 and lane/4+8) ----
        float mx0 = s[0][0], mx1 = s[0][2];
#pragma unroll
        for (int nt = 0; nt < 4; nt++) {
            mx0 = fmaxf(mx0, fmaxf(s[nt][0], s[nt][1]));
            mx1 = fmaxf(mx1, fmaxf(s[nt][2], s[nt][3]));
        }
        mx0 = fmaxf(mx0, __shfl_xor_sync(0xffffffffu, mx0, 1));
        mx0 = fmaxf(mx0, __shfl_xor_sync(0xffffffffu, mx0, 2));
        mx1 = fmaxf(mx1, __shfl_xor_sync(0xffffffffu, mx1, 1));
        mx1 = fmaxf(mx1, __shfl_xor_sync(0xffffffffu, mx1, 2));

        float mn0 = fmaxf(m0r, mx0), mn1 = fmaxf(m1r, mx1);
        float sc0 = __expf(m0r - mn0), sc1 = __expf(m1r - mn1);
        m0r = mn0; m1r = mn1;

        float rs0 = 0.0f, rs1 = 0.0f;
#pragma unroll
        for (int nt = 0; nt < 4; nt++) {
            s[nt][0] = __expf(s[nt][0] - mn0);
            s[nt][1] = __expf(s[nt][1] - mn0);
            s[nt][2] = __expf(s[nt][2] - mn1);
            s[nt][3] = __expf(s[nt][3] - mn1);
            rs0 += s[nt][0] + s[nt][1];
            rs1 += s[nt][2] + s[nt][3];
        }
        rs0 += __shfl_xor_sync(0xffffffffu, rs0, 1);
        rs0 += __shfl_xor_sync(0xffffffffu, rs0, 2);
        rs1 += __shfl_xor_sync(0xffffffffu, rs1, 1);
        rs1 += __shfl_xor_sync(0xffffffffu, rs1, 2);
        l0r = l0r * sc0 + rs0;
        l1r = l1r * sc1 + rs1;

#pragma unroll
        for (int nt = 0; nt < 32; nt++) {
            o[nt][0] *= sc0; o[nt][1] *= sc0;
            o[nt][2] *= sc1; o[nt][3] *= sc1;
        }

        // P (C-fragments) -> A-fragments, bf16 hi/lo split
        uint32_t ph[2][4], pl[2][4];
#pragma unroll
        for (int kc = 0; kc < 2; kc++) {
            int nt0 = 2 * kc, nt1 = 2 * kc + 1;
            split2(s[nt0][0], s[nt0][1], ph[kc][0], pl[kc][0]);
            split2(s[nt0][2], s[nt0][3], ph[kc][1], pl[kc][1]);
            split2(s[nt1][0], s[nt1][1], ph[kc][2], pl[kc][2]);
            split2(s[nt1][2], s[nt1][3], ph[kc][3], pl[kc][3]);
        }

        // ---- O += P V ----
#pragma unroll
        for (int kc = 0; kc < 2; kc++) {
#pragma unroll
            for (int ct = 0; ct < 16; ct++) {
                uint32_t vh[4], vl[4];
                ldsm4t(vh, aVh + kc * (16 * SQ * 2) + ct * 32);
                ldsm4t(vl, aVl + kc * (16 * SQ * 2) + ct * 32);
                float* oA = o[2 * ct];
                float* oB = o[2 * ct + 1];
                mma16816(oA, ph[kc], vh[0], vh[1]);
                mma16816(oA, ph[kc], vl[0], vl[1]);
                mma16816(oA, pl[kc], vh[0], vh[1]);
                mma16816(oB, ph[kc], vh[2], vh[3]);
                mma16816(oB, ph[kc], vl[2], vl[3]);
                mma16816(oB, pl[kc], vh[2], vh[3]);
            }
        }
    }

    // ---- epilogue: normalize, store fp32 rows to g_a ----
    float inv0 = 1.0f / l0r, inv1 = 1.0f / l1r;
    int r0 = n0 + w * 16 + (lane >> 2);
    int r1 = r0 + 8;
    int cb = (lane & 3) * 2;
    float* A = g_a + base;
#pragma unroll
    for (int nt = 0; nt < 32; nt++) {
        int c = nt * 8 + cb;
        float2 v0 = make_float2(o[nt][0] * inv0, o[nt][1] * inv0);
        float2 v1 = make_float2(o[nt][2] * inv1, o[nt][3] * inv1);
        *(float2*)&A[(size_t)r0 * 256 + c] = v0;
        *(float2*)&A[(size_t)r1 * 256 + c] = v1;
    }
}

// ---------------------------------------------------------------------------
// Kernel 3: out = x + Wu * attn + bu
// ---------------------------------------------------------------------------
__global__ __launch_bounds__(256) void out_kernel(
    const float* __restrict__ x, const float* __restrict__ Wu,
    const float* __restrict__ bu, float* __restrict__ out)
{
    __shared__ float Ws[16][68];
    __shared__ float Xs[16][128];

    int b = blockIdx.z;
    int m0 = blockIdx.y * 64;
    int s0 = blockIdx.x * 128;
    int tid = threadIdx.x;
    int ty = tid >> 4, tx = tid & 15;

    float acc[4][8];
#pragma unroll
    for (int i = 0; i < 4; i++)
#pragma unroll
        for (int j = 0; j < 8; j++) acc[i][j] = 0.0f;

    const float* Ab = g_a + (size_t)b * CH * SP;

    for (int k0 = 0; k0 < CH; k0 += 16) {
        {
            int mm = tid & 63, kk4 = (tid >> 6) << 2;
            float4 wv = *(const float4*)&Wu[(m0 + mm) * CH + k0 + kk4];
            Ws[kk4 + 0][mm] = wv.x;
            Ws[kk4 + 1][mm] = wv.y;
            Ws[kk4 + 2][mm] = wv.z;
            Ws[kk4 + 3][mm] = wv.w;
        }
        {
            int kk = tid >> 4, nn = (tid & 15) * 8;
            const float* ap = Ab + (size_t)(k0 + kk) * SP + s0 + nn;
            *(float4*)&Xs[kk][nn]     = *(const float4*)ap;
            *(float4*)&Xs[kk][nn + 4] = *(const float4*)(ap + 4);
        }
        __syncthreads();
#pragma unroll
        for (int k = 0; k < 16; k++) {
            float4 a  = *(const float4*)&Ws[k][ty * 4];
            float4 b0 = *(const float4*)&Xs[k][tx * 8];
            float4 b1 = *(const float4*)&Xs[k][tx * 8 + 4];
            float av[4] = {a.x, a.y, a.z, a.w};
            float bw[8] = {b0.x, b0.y, b0.z, b0.w, b1.x, b1.y, b1.z, b1.w};
#pragma unroll
            for (int i = 0; i < 4; i++)
#pragma unroll
                for (int j = 0; j < 8; j++)
                    acc[i][j] = fmaf(av[i], bw[j], acc[i][j]);
        }
        __syncthreads();
    }

#pragma unroll
    for (int i = 0; i < 4; i++) {
        int m = m0 + ty * 4 + i;
        float bi = bu[m];
        size_t bo = (size_t)b * CH * SP + (size_t)m * SP + s0 + tx * 8;
        float4 x0 = *(const float4*)&x[bo];
        float4 x1 = *(const float4*)&x[bo + 4];
        float4 r0, r1;
        r0.x = acc[i][0] + bi + x0.x; r0.y = acc[i][1] + bi + x0.y;
        r0.z = acc[i][2] + bi + x0.z; r0.w = acc[i][3] + bi + x0.w;
        r1.x = acc[i][4] + bi + x1.x; r1.y = acc[i][5] + bi + x1.y;
        r1.z = acc[i][6] + bi + x1.z; r1.w = acc[i][7] + bi + x1.w;
        *(float4*)&out[bo]     = r0;
        *(float4*)&out[bo + 4] = r1;
    }
}

// ---------------------------------------------------------------------------
extern "C" void kernel_launch(void* const* d_in, const int* in_sizes, int n_in,
                              void* d_out, int out_size)
{
    (void)in_sizes; (void)n_in; (void)out_size;
    const float* x  = (const float*)d_in[0];
    const float* Wq = (const float*)d_in[1];
    const float* bq = (const float*)d_in[2];
    const float* Wk = (const float*)d_in[3];
    const float* bk = (const float*)d_in[4];
    const float* Wv = (const float*)d_in[5];
    const float* bv = (const float*)d_in[6];
    const float* Wu = (const float*)d_in[7];
    const float* bu = (const float*)d_in[8];
    float* out = (float*)d_out;

    cudaFuncSetAttribute(attn_kernel, cudaFuncAttributeMaxDynamicSharedMemorySize, ATTN_SMEM);

    qkv_kernel<<<dim3(32, 4, 12), 256>>>(x, Wq, bq, Wk, bk, Wv, bv);
    attn_kernel<<<dim3(32, 4), 256, ATTN_SMEM>>>();
    out_kernel<<<dim3(32, 4, 4), 256>>>(x, Wu, bu, out);
}